// round 14
// baseline (speedup 1.0000x reference)
#include <cuda_runtime.h>
#include <math.h>
#include <stdint.h>

// Problem constants
#define B_   8
#define N_   512
#define D_   256
#define R_   6
#define BN_  (B_*N_)          // 4096 rows
#define KA_  1568             // 6*256 rel cols + 6 count cols + pad

// Output layout in d_out (floats)
#define OFF_INTERP 1048576
#define OFF_SYM    (1048576 + 3*4096)

// ---------------- scratch ----------------
__device__ float    g_S0[BN_ * D_];
__device__ float    g_A[BN_ * KA_];
__device__ float    g_Wfull[KA_ * D_];
__device__ float    g_Wcat[D_ * 4 * D_];    // [k][1024]: 3 head W's + outW
__device__ float    g_bcat[4 * D_];
__device__ float    g_H[BN_ * 3 * D_];
__device__ float    g_P[B_ * (N_ + 1) * D_];
__device__ int      g_sidx[B_ * N_];        // sorted pos -> original index
__device__ int      g_k0s[B_ * N_];         // band bounds per SORTED index
__device__ int      g_k1s[B_ * N_];
__device__ uint32_t g_mask[3 * B_ * N_ * 16];  // bit per (js,m): r=2,3,4

// ---------------- embed ----------------
__global__ void k_embed(const int* __restrict__ ids,
                        const float* __restrict__ symt,
                        const float* __restrict__ layt) {
    int row = blockIdx.x, t = threadIdx.x;
    int id  = ids[row];
    g_S0[row * D_ + t] = symt[id * D_ + t] + layt[id * D_ + t];
}

// ---------------- sort + band bounds + bitmasks ----------------
// Per batch: bitonic sort y, binary-search band, then build band-restricted
// bit masks for relations 2/3/4 in SORTED (js, m) space. Within the band
// [k0,k1), |dy|<=0.5 is guaranteed, so only dx tests + small-box remain.
__global__ void k_sort(const float* __restrict__ pos) {
    __shared__ float key[N_];
    __shared__ int   val[N_];
    __shared__ float xs[N_];
    int b = blockIdx.x, t = threadIdx.x;
    key[t] = pos[(b * N_ + t) * 2 + 1];
    val[t] = t;
    __syncthreads();
    for (int size = 2; size <= N_; size <<= 1) {
        for (int stride = size >> 1; stride > 0; stride >>= 1) {
            int j = t ^ stride;
            if (j > t) {
                bool up = ((t & size) == 0);
                float kt = key[t], kj = key[j];
                if ((kt > kj) == up) {
                    key[t] = kj; key[j] = kt;
                    int vt = val[t]; val[t] = val[j]; val[j] = vt;
                }
            }
            __syncthreads();
        }
    }
    g_sidx[b * N_ + t] = val[t];
    xs[t] = pos[(b * N_ + val[t]) * 2 + 0];
    float y  = key[t];
    float v0 = y - 0.5f, v1 = y + 0.5f;
    int lo = 0, hi = N_;
    while (lo < hi) { int m = (lo + hi) >> 1; if (key[m] <  v0) lo = m + 1; else hi = m; }
    int k0 = lo;
    lo = 0; hi = N_;
    while (lo < hi) { int m = (lo + hi) >> 1; if (key[m] <= v1) lo = m + 1; else hi = m; }
    int k1 = lo;
    g_k0s[b * N_ + t] = k0;
    g_k1s[b * N_ + t] = k1;
    __syncthreads();

    float xj = xs[t];
    int w0 = k0 >> 5, w1 = (k1 + 31) >> 5;
    uint32_t* M2 = &g_mask[((0 * B_ + b) * N_ + t) * 16];
    uint32_t* M3 = &g_mask[((1 * B_ + b) * N_ + t) * 16];
    uint32_t* M4 = &g_mask[((2 * B_ + b) * N_ + t) * 16];
    for (int w = 0; w < 16; w++) {
        uint32_t b2 = 0, b3 = 0, b4 = 0;
        if (w >= w0 && w < w1) {
            int mbase = w * 32;
#pragma unroll 4
            for (int u = 0; u < 32; u++) {
                int m = mbase + u;
                if (m >= k0 && m < k1 && m != t) {
                    float dx = xj - xs[m];
                    float dy = y - key[m];
                    if (dx < -0.5f)      b2 |= 1u << u;
                    else if (dx > 0.5f)  b3 |= 1u << u;
                    else if (fabsf(dx) < 0.3f && fabsf(dy) < 0.3f) b4 |= 1u << u;
                }
            }
        }
        M2[w] = b2; M3[w] = b3; M4[w] = b4;
    }
}

// parallel prefix: grid = B*8 (32-ch groups), block = 1024 (32 warps x 16 serial rows)
__global__ void __launch_bounds__(1024) k_prefix() {
    __shared__ float ssum[32][33];
    int b    = blockIdx.x >> 3;
    int g    = blockIdx.x & 7;
    int lane = threadIdx.x & 31;
    int w    = threadIdx.x >> 5;
    int ch   = g * 32 + lane;
    const int* si = &g_sidx[b * N_];
    int m0 = w * 16;
    float s = 0.f;
#pragma unroll
    for (int m = 0; m < 16; m++)
        s += g_S0[(b * N_ + si[m0 + m]) * D_ + ch];
    ssum[w][lane] = s;
    __syncthreads();
    float run = 0.f;
    for (int q = 0; q < w; q++) run += ssum[q][lane];
    float* Pb = &g_P[(size_t)(b * (N_ + 1)) * D_ + ch];
#pragma unroll
    for (int m = 0; m < 16; m++) {
        Pb[(size_t)(m0 + m) * D_] = run;
        run += g_S0[(b * N_ + si[m0 + m]) * D_ + ch];
    }
    if (w == 31) Pb[(size_t)N_ * D_] = run;
}

// merged weight-prep: Wfull (grammar) + Wcat/bcat (heads+out)
__global__ void k_weights(const float* __restrict__ relW, const float* __restrict__ relb,
                          const float* __restrict__ h1W, const float* __restrict__ h1b,
                          const float* __restrict__ outW, const float* __restrict__ outb) {
    const int W1 = KA_ * D_;
    const int W2 = W1 + 1024 * D_;
    int idx = blockIdx.x * 256 + threadIdx.x;
    if (idx < W1) {
        int row = idx / D_, e = idx % D_;
        float v;
        if (row < R_ * D_)            v = relW[idx];
        else if (row < R_ * D_ + R_)  v = relb[(row - R_ * D_) * D_ + e];
        else                          v = 0.f;
        g_Wfull[idx] = v;
    } else if (idx < W2) {
        int i = idx - W1;
        int k = i >> 10, n = i & 1023;
        g_Wcat[i] = (n < 768) ? h1W[((n >> 8) * D_ + k) * D_ + (n & 255)]
                              : outW[k * D_ + (n - 768)];
    } else if (idx < W2 + 1024) {
        int i = idx - W2;
        g_bcat[i] = (i < 768) ? h1b[(i >> 8) * D_ + (i & 255)] : outb[i - 768];
    }
}

// ---------------- tf32 helpers ----------------
__device__ __forceinline__ uint32_t f2tf32(float x) {
    uint32_t r;
    asm("cvt.rna.tf32.f32 %0, %1;" : "=r"(r) : "f"(x));
    return r;
}

__device__ __forceinline__ void mma_tf32(float* c, uint32_t a0, uint32_t a1,
                                         uint32_t a2, uint32_t a3,
                                         uint32_t b0, uint32_t b1) {
    asm volatile(
        "mma.sync.aligned.m16n8k8.row.col.f32.tf32.tf32.f32 "
        "{%0,%1,%2,%3}, {%4,%5,%6,%7}, {%8,%9}, {%0,%1,%2,%3};"
        : "+f"(c[0]), "+f"(c[1]), "+f"(c[2]), "+f"(c[3])
        : "r"(a0), "r"(a1), "r"(a2), "r"(a3), "r"(b0), "r"(b1));
}

// ---------------- band-restricted bitmask GEMM + A-row epilogue ----------------
// grid (8 ch-tiles of 32, 8 j-tiles of 64 SORTED rows, 8 b), 256 thr
// (8 warps: 4 j-slabs x 2 ch-slabs). K loop restricted to tile's union band.
__global__ void __launch_bounds__(256, 4) k_mgband() {
    __shared__ uint32_t BsH[32 * 36];
    __shared__ uint32_t mw[3][64];
    __shared__ int      sk0[64], sk1[64], ssid[64];
    __shared__ int      s_lo, s_hi;

    int b   = blockIdx.z;
    int j0  = blockIdx.y * 64;
    int ch0 = blockIdx.x * 32;
    int t    = threadIdx.x;
    int warp = t >> 5, lane = t & 31;
    int wm = warp >> 1;              // 0..3 -> 16-row j slab
    int wn = warp & 1;               // 0..1 -> 16-col ch slab
    int qr = lane >> 2, qc = lane & 3;
    bool count_blk = (blockIdx.x == 0);

    if (t < 64) {
        sk0[t]  = g_k0s[b * N_ + j0 + t];
        sk1[t]  = g_k1s[b * N_ + j0 + t];
        ssid[t] = g_sidx[b * N_ + j0 + t];
    }
    __syncthreads();
    if (t < 32) {
        int lo = min(sk0[t], sk0[t + 32]);
        int hi = max(sk1[t], sk1[t + 32]);
#pragma unroll
        for (int o = 16; o; o >>= 1) {
            lo = min(lo, __shfl_xor_sync(0xffffffffu, lo, o));
            hi = max(hi, __shfl_xor_sync(0xffffffffu, hi, o));
        }
        if (t == 0) { s_lo = lo & ~31; s_hi = hi; }
    }
    __syncthreads();
    int klo = s_lo, khi = s_hi;

    float acc[3][2][4];
#pragma unroll
    for (int r = 0; r < 3; r++)
#pragma unroll
        for (int nt = 0; nt < 2; nt++)
#pragma unroll
            for (int f = 0; f < 4; f++) acc[r][nt][f] = 0.f;

    const uint32_t ONE = 0x3F800000u;
    int rb = wm * 16 + qr;

    for (int kt = klo; kt < khi; kt += 32) {
        int w = kt >> 5;
        // stage mask words: one per (r, j)
        if (t < 192) {
            int r = t >> 6, j = t & 63;
            mw[r][j] = g_mask[((size_t)(r * B_ + b) * N_ + j0 + j) * 16 + w];
        }
        // stage S0 sorted rows [32 m x 32 ch] (hi only) as [n][k], stride 36
#pragma unroll
        for (int l = 0; l < 4; l++) {
            int id = t + l * 256;
            int k  = id >> 5, n = id & 31;
            int row = g_sidx[b * N_ + kt + k];
            float v = g_S0[(size_t)(b * N_ + row) * D_ + ch0 + n];
            BsH[n * 36 + k] = f2tf32(v);
        }
        __syncthreads();

        uint32_t s2a = mw[0][rb] >> qc, s2b = mw[0][rb + 8] >> qc;
        uint32_t s3a = mw[1][rb] >> qc, s3b = mw[1][rb + 8] >> qc;
        uint32_t s4a = mw[2][rb] >> qc, s4b = mw[2][rb + 8] >> qc;

#pragma unroll
        for (int ks = 0; ks < 32; ks += 8) {
            int k0 = ks + qc;
            uint32_t bh[4];
#pragma unroll
            for (int nt = 0; nt < 2; nt++) {
                int nb = wn * 16 + nt * 8 + qr;
                bh[nt*2+0] = BsH[nb * 36 + k0];
                bh[nt*2+1] = BsH[nb * 36 + k0 + 4];
            }
            {
                uint32_t a0 = ((s2a >> ks) & 1u)       ? ONE : 0u;
                uint32_t a1 = ((s2b >> ks) & 1u)       ? ONE : 0u;
                uint32_t a2 = ((s2a >> (ks + 4)) & 1u) ? ONE : 0u;
                uint32_t a3 = ((s2b >> (ks + 4)) & 1u) ? ONE : 0u;
                mma_tf32(acc[0][0], a0, a1, a2, a3, bh[0], bh[1]);
                mma_tf32(acc[0][1], a0, a1, a2, a3, bh[2], bh[3]);
            }
            {
                uint32_t a0 = ((s3a >> ks) & 1u)       ? ONE : 0u;
                uint32_t a1 = ((s3b >> ks) & 1u)       ? ONE : 0u;
                uint32_t a2 = ((s3a >> (ks + 4)) & 1u) ? ONE : 0u;
                uint32_t a3 = ((s3b >> (ks + 4)) & 1u) ? ONE : 0u;
                mma_tf32(acc[1][0], a0, a1, a2, a3, bh[0], bh[1]);
                mma_tf32(acc[1][1], a0, a1, a2, a3, bh[2], bh[3]);
            }
            {
                uint32_t a0 = ((s4a >> ks) & 1u)       ? ONE : 0u;
                uint32_t a1 = ((s4b >> ks) & 1u)       ? ONE : 0u;
                uint32_t a2 = ((s4a >> (ks + 4)) & 1u) ? ONE : 0u;
                uint32_t a3 = ((s4b >> (ks + 4)) & 1u) ? ONE : 0u;
                mma_tf32(acc[2][0], a0, a1, a2, a3, bh[0], bh[1]);
                mma_tf32(acc[2][1], a0, a1, a2, a3, bh[2], bh[3]);
            }
        }
        __syncthreads();
    }

    // epilogue: write all 6 relation segments into original-index A rows
    const float* Pb = &g_P[(size_t)(b * (N_ + 1)) * D_];
#pragma unroll
    for (int f = 0; f < 4; f++) {
        int rl  = wm * 16 + qr + ((f >= 2) ? 8 : 0);
        int oj  = ssid[rl];
        int k0r = sk0[rl], k1r = sk1[rl];
        int grow = b * N_ + oj;
        float* Ar = &g_A[(size_t)grow * KA_];
#pragma unroll
        for (int nt = 0; nt < 2; nt++) {
            int col = ch0 + wn * 16 + nt * 8 + qc * 2 + (f & 1);
            float p0  = Pb[(size_t)k0r * D_ + col];
            float p1  = Pb[(size_t)k1r * D_ + col];
            float tot = Pb[(size_t)N_ * D_ + col];
            float sj  = g_S0[(size_t)grow * D_ + col];
            float a2v = acc[0][nt][f];
            float a3v = acc[1][nt][f];
            float a4v = acc[2][nt][f];
            Ar[0 * D_ + col] = p0;
            Ar[1 * D_ + col] = tot - p1;
            Ar[2 * D_ + col] = a2v;
            Ar[3 * D_ + col] = a3v;
            Ar[4 * D_ + col] = a4v;
            Ar[5 * D_ + col] = (p1 - p0 - sj) - a2v - a3v - a4v;
        }
    }
    if (count_blk && t < 64) {
        int k0r = sk0[t], k1r = sk1[t];
        int w0 = k0r >> 5, w1 = (k1r + 31) >> 5;
        int n2 = 0, n3 = 0, n4 = 0;
        for (int w = w0; w < w1; w++) {
            n2 += __popc(g_mask[((size_t)(0 * B_ + b) * N_ + j0 + t) * 16 + w]);
            n3 += __popc(g_mask[((size_t)(1 * B_ + b) * N_ + j0 + t) * 16 + w]);
            n4 += __popc(g_mask[((size_t)(2 * B_ + b) * N_ + j0 + t) * 16 + w]);
        }
        int oj = ssid[t];
        float* Ar = &g_A[(size_t)(b * N_ + oj) * KA_ + R_ * D_];
#pragma unroll
        for (int c = 0; c < 32; c++) {
            float cv = 0.f;
            if (c == 0)      cv = (float)k0r;
            else if (c == 1) cv = (float)(N_ - k1r);
            else if (c == 2) cv = (float)n2;
            else if (c == 3) cv = (float)n3;
            else if (c == 4) cv = (float)n4;
            else if (c == 5) cv = (float)((k1r - k0r - 1) - n2 - n3 - n4);
            Ar[c] = cv;
        }
    }
}

// ---------------- main GEMMs (tf32 3-pass, hi/lo split smem) ----------------
// MODE 0: C = A@Bm + addp  (grammar)
// MODE 1: fused heads+out  (cols<768: gelu -> C(ld 768); else -> C2(ld 256))
template<int MODE, int BNt>
__global__ void __launch_bounds__(256) mgemm2(
        const float* __restrict__ A, int lda,
        const float* __restrict__ Bm, int ldb, int K,
        const float* __restrict__ addp,
        float* __restrict__ C, float* __restrict__ C2) {
    constexpr int HALF = BNt / 2;
    constexpr int NT   = HALF / 8;
    extern __shared__ uint32_t sm[];
    uint32_t* AsH = sm;
    uint32_t* AsL = sm + 128 * 36;
    uint32_t* BsH = sm + 2 * 128 * 36;
    uint32_t* BsL = BsH + BNt * 36;

    int t    = threadIdx.x;
    int warp = t >> 5, lane = t & 31;
    int wm   = warp >> 1;
    int wn   = warp & 1;
    int bm0  = blockIdx.y * 128;
    int bn0  = blockIdx.x * BNt;
    int qr   = lane >> 2;
    int qc   = lane & 3;

    float acc[2][NT][4];
#pragma unroll
    for (int mt = 0; mt < 2; mt++)
#pragma unroll
        for (int nt = 0; nt < NT; nt++)
#pragma unroll
            for (int f = 0; f < 4; f++) acc[mt][nt][f] = 0.f;

    for (int kt = 0; kt < K; kt += 32) {
#pragma unroll
        for (int l = 0; l < 4; l++) {
            int id  = t + l * 256;
            int row = id >> 3;
            int kq  = (id & 7) * 4;
            float4 v = *(const float4*)&A[(size_t)(bm0 + row) * lda + kt + kq];
            float fe[4] = {v.x, v.y, v.z, v.w};
#pragma unroll
            for (int jj = 0; jj < 4; jj++) {
                uint32_t h = f2tf32(fe[jj]);
                AsH[row * 36 + kq + jj] = h;
                AsL[row * 36 + kq + jj] = f2tf32(fe[jj] - __uint_as_float(h));
            }
        }
#pragma unroll
        for (int l = 0; l < (BNt * 32) / 256; l++) {
            int id = t + l * 256;
            int k  = id / BNt;
            int n  = id % BNt;
            float v = Bm[(size_t)(kt + k) * ldb + bn0 + n];
            uint32_t h = f2tf32(v);
            BsH[n * 36 + k] = h;
            BsL[n * 36 + k] = f2tf32(v - __uint_as_float(h));
        }
        __syncthreads();

#pragma unroll
        for (int ks = 0; ks < 32; ks += 8) {
            int k0 = ks + qc;
            uint32_t ahi[8], alo[8];
#pragma unroll
            for (int mt = 0; mt < 2; mt++) {
                int rb = wm * 32 + mt * 16 + qr;
                ahi[mt*4+0] = AsH[rb * 36 + k0];
                ahi[mt*4+1] = AsH[(rb + 8) * 36 + k0];
                ahi[mt*4+2] = AsH[rb * 36 + k0 + 4];
                ahi[mt*4+3] = AsH[(rb + 8) * 36 + k0 + 4];
                alo[mt*4+0] = AsL[rb * 36 + k0];
                alo[mt*4+1] = AsL[(rb + 8) * 36 + k0];
                alo[mt*4+2] = AsL[rb * 36 + k0 + 4];
                alo[mt*4+3] = AsL[(rb + 8) * 36 + k0 + 4];
            }
            uint32_t bhi[2*NT], blo[2*NT];
#pragma unroll
            for (int nt = 0; nt < NT; nt++) {
                int nb = wn * HALF + nt * 8 + qr;
                bhi[nt*2+0] = BsH[nb * 36 + k0];
                bhi[nt*2+1] = BsH[nb * 36 + k0 + 4];
                blo[nt*2+0] = BsL[nb * 36 + k0];
                blo[nt*2+1] = BsL[nb * 36 + k0 + 4];
            }
#pragma unroll
            for (int mt = 0; mt < 2; mt++)
#pragma unroll
                for (int nt = 0; nt < NT; nt++) {
                    float* c = acc[mt][nt];
                    mma_tf32(c, ahi[mt*4], ahi[mt*4+1], ahi[mt*4+2], ahi[mt*4+3],
                             bhi[nt*2], bhi[nt*2+1]);
                    mma_tf32(c, alo[mt*4], alo[mt*4+1], alo[mt*4+2], alo[mt*4+3],
                             bhi[nt*2], bhi[nt*2+1]);
                    mma_tf32(c, ahi[mt*4], ahi[mt*4+1], ahi[mt*4+2], ahi[mt*4+3],
                             blo[nt*2], blo[nt*2+1]);
                }
        }
        __syncthreads();
    }

#pragma unroll
    for (int mt = 0; mt < 2; mt++) {
#pragma unroll
        for (int f = 0; f < 4; f++) {
            int row = bm0 + wm * 32 + mt * 16 + qr + ((f >= 2) ? 8 : 0);
#pragma unroll
            for (int nt = 0; nt < NT; nt++) {
                int col = bn0 + wn * HALF + nt * 8 + qc * 2 + (f & 1);
                float v = acc[mt][nt][f];
                if (MODE == 0) {
                    v += addp[(size_t)row * D_ + col];
                    C[(size_t)row * D_ + col] = v;
                } else {
                    v += g_bcat[col];
                    if (bn0 < 768) {
                        v = 0.5f * v * (1.f + erff(v * 0.70710678118654752440f));
                        C[(size_t)row * 768 + col] = v;
                    } else {
                        C2[(size_t)row * D_ + (col - 768)] = v;
                    }
                }
            }
        }
    }
}

__global__ void k_interp(const float* __restrict__ h2W, const float* __restrict__ h2b,
                         float* __restrict__ out) {
    int row  = blockIdx.x;
    int wid  = threadIdx.x >> 5;
    int lane = threadIdx.x & 31;
    const float* hrow = &g_H[(size_t)row * (3 * D_) + wid * D_];
    const float* w    = &h2W[wid * D_];
    float s = 0.f;
    for (int e = lane; e < D_; e += 32) s += hrow[e] * w[e];
#pragma unroll
    for (int o = 16; o; o >>= 1) s += __shfl_xor_sync(0xffffffffu, s, o);
    if (lane == 0) out[OFF_INTERP + wid * BN_ + row] = s + h2b[wid];
}

// ---------------- launch ----------------
#define SMB(BNt) ((2*128*36 + 2*(BNt)*36) * 4)

extern "C" void kernel_launch(void* const* d_in, const int* in_sizes, int n_in,
                              void* d_out, int out_size) {
    const int*   ids  = (const int*)  d_in[0];
    const float* pos  = (const float*)d_in[1];
    const float* symt = (const float*)d_in[2];
    const float* layt = (const float*)d_in[3];
    const float* relW = (const float*)d_in[4];
    const float* relb = (const float*)d_in[5];
    const float* h1W  = (const float*)d_in[6];
    const float* h1b  = (const float*)d_in[7];
    const float* h2W  = (const float*)d_in[8];
    const float* h2b  = (const float*)d_in[9];
    const float* outW = (const float*)d_in[10];
    const float* outb = (const float*)d_in[11];
    float* out = (float*)d_out;

    float *pA, *pW, *pWc, *pH, *pS0;
    cudaGetSymbolAddress((void**)&pA,  g_A);
    cudaGetSymbolAddress((void**)&pW,  g_Wfull);
    cudaGetSymbolAddress((void**)&pWc, g_Wcat);
    cudaGetSymbolAddress((void**)&pH,  g_H);
    cudaGetSymbolAddress((void**)&pS0, g_S0);

    cudaFuncSetAttribute((const void*)mgemm2<0,32>,
                         cudaFuncAttributeMaxDynamicSharedMemorySize, SMB(32));
    cudaFuncSetAttribute((const void*)mgemm2<1,64>,
                         cudaFuncAttributeMaxDynamicSharedMemorySize, SMB(64));

    // order: slot #3 (0-indexed) = k_mgband -> profiled by ncu
    k_embed <<<BN_, D_>>>(ids, symt, layt);
    k_sort  <<<B_, N_>>>(pos);
    k_prefix<<<B_ * 8, 1024>>>();
    k_mgband<<<dim3(8, 8, 8), 256>>>();
    {
        int total = KA_ * D_ + 1024 * D_ + 1024;
        k_weights<<<(total + 255) / 256, 256>>>(relW, relb, h1W, h1b, outW, outb);
    }

    float* d_sym = out + OFF_SYM;
    // grammar: symbols = S0 + A @ Wfull  (BN=32 -> 256 blocks)
    mgemm2<0,32><<<dim3(D_ / 32, BN_ / 128), 256, SMB(32)>>>(
        pA, KA_, pW, D_, KA_, pS0, d_sym, nullptr);
    // fused heads (gelu -> g_H) + output projection (-> out)
    mgemm2<1,64><<<dim3(1024 / 64, BN_ / 128), 256, SMB(64)>>>(
        d_sym, D_, pWc, 1024, D_, nullptr, pH, out);

    k_interp<<<BN_, 96>>>(h2W, h2b, out);
}

// round 17
// speedup vs baseline: 1.0356x; 1.0356x over previous
#include <cuda_runtime.h>
#include <math.h>
#include <stdint.h>

// Problem constants
#define B_   8
#define N_   512
#define D_   256
#define R_   6
#define BN_  (B_*N_)          // 4096 rows
#define KA_  1568             // 6*256 rel cols + 6 count cols + pad

// Output layout in d_out (floats)
#define OFF_INTERP 1048576
#define OFF_SYM    (1048576 + 3*4096)

// ---------------- scratch ----------------
__device__ float    g_S0[BN_ * D_];
__device__ float    g_A[BN_ * KA_];
__device__ float    g_Wfull[KA_ * D_];
__device__ float    g_Wcat[D_ * 4 * D_];    // [k][1024]: 3 head W's + outW
__device__ float    g_bcat[4 * D_];
__device__ float    g_H[BN_ * 3 * D_];
__device__ float    g_P[B_ * (N_ + 1) * D_];
__device__ int      g_sidx[B_ * N_];        // sorted pos -> original index
__device__ int      g_k0s[B_ * N_];         // band bounds per SORTED index
__device__ int      g_k1s[B_ * N_];
__device__ float    g_xsort[B_ * N_];       // x, y in sorted order
__device__ float    g_ysort[B_ * N_];
__device__ uint32_t g_mask[3 * B_ * N_ * 16];  // bit per (js,m): r=2,3,4

// ---------------- embed ----------------
__global__ void k_embed(const int* __restrict__ ids,
                        const float* __restrict__ symt,
                        const float* __restrict__ layt) {
    int row = blockIdx.x, t = threadIdx.x;
    int id  = ids[row];
    g_S0[row * D_ + t] = symt[id * D_ + t] + layt[id * D_ + t];
}

// ---------------- sort + band bounds ----------------
__global__ void k_sort(const float* __restrict__ pos) {
    __shared__ float key[N_];
    __shared__ int   val[N_];
    int b = blockIdx.x, t = threadIdx.x;
    key[t] = pos[(b * N_ + t) * 2 + 1];
    val[t] = t;
    __syncthreads();
    for (int size = 2; size <= N_; size <<= 1) {
        for (int stride = size >> 1; stride > 0; stride >>= 1) {
            int j = t ^ stride;
            if (j > t) {
                bool up = ((t & size) == 0);
                float kt = key[t], kj = key[j];
                if ((kt > kj) == up) {
                    key[t] = kj; key[j] = kt;
                    int vt = val[t]; val[t] = val[j]; val[j] = vt;
                }
            }
            __syncthreads();
        }
    }
    g_sidx[b * N_ + t]  = val[t];
    g_ysort[b * N_ + t] = key[t];
    g_xsort[b * N_ + t] = pos[(b * N_ + val[t]) * 2 + 0];
    float y  = key[t];
    float v0 = y - 0.5f, v1 = y + 0.5f;
    int lo = 0, hi = N_;
    while (lo < hi) { int m = (lo + hi) >> 1; if (key[m] <  v0) lo = m + 1; else hi = m; }
    int k0 = lo;
    lo = 0; hi = N_;
    while (lo < hi) { int m = (lo + hi) >> 1; if (key[m] <= v1) lo = m + 1; else hi = m; }
    g_k0s[b * N_ + t] = k0;
    g_k1s[b * N_ + t] = lo;
}

// ---------------- bitmask builder (wide) ----------------
// grid (16 j-tiles, 8 b), 256 thr. Each work item = (j, word). Band-restricted.
__global__ void k_maskb() {
    __shared__ float xs[N_], ys[N_];
    int b  = blockIdx.y;
    int j0 = blockIdx.x * 32;
    int t  = threadIdx.x;
    for (int i = t; i < N_; i += 256) {
        xs[i] = g_xsort[b * N_ + i];
        ys[i] = g_ysort[b * N_ + i];
    }
    __syncthreads();
    for (int idx = t; idx < 32 * 16; idx += 256) {
        int jl = idx >> 4, w = idx & 15;
        int j  = j0 + jl;
        int k0 = g_k0s[b * N_ + j], k1 = g_k1s[b * N_ + j];
        uint32_t b2 = 0, b3 = 0, b4 = 0;
        int w0 = k0 >> 5, w1 = (k1 + 31) >> 5;
        if (w >= w0 && w < w1) {
            float xj = xs[j], yj = ys[j];
            int mbase = w * 32;
#pragma unroll 4
            for (int u = 0; u < 32; u++) {
                int m = mbase + u;
                if (m >= k0 && m < k1 && m != j) {
                    float dx = xj - xs[m];
                    float dy = yj - ys[m];
                    if (dx < -0.5f)      b2 |= 1u << u;
                    else if (dx > 0.5f)  b3 |= 1u << u;
                    else if (fabsf(dx) < 0.3f && fabsf(dy) < 0.3f) b4 |= 1u << u;
                }
            }
        }
        g_mask[((size_t)(0 * B_ + b) * N_ + j) * 16 + w] = b2;
        g_mask[((size_t)(1 * B_ + b) * N_ + j) * 16 + w] = b3;
        g_mask[((size_t)(2 * B_ + b) * N_ + j) * 16 + w] = b4;
    }
}

// parallel prefix: grid = B*8 (32-ch groups), block = 1024 (32 warps x 16 serial rows)
__global__ void __launch_bounds__(1024) k_prefix() {
    __shared__ float ssum[32][33];
    int b    = blockIdx.x >> 3;
    int g    = blockIdx.x & 7;
    int lane = threadIdx.x & 31;
    int w    = threadIdx.x >> 5;
    int ch   = g * 32 + lane;
    const int* si = &g_sidx[b * N_];
    int m0 = w * 16;
    float s = 0.f;
#pragma unroll
    for (int m = 0; m < 16; m++)
        s += g_S0[(b * N_ + si[m0 + m]) * D_ + ch];
    ssum[w][lane] = s;
    __syncthreads();
    float run = 0.f;
    for (int q = 0; q < w; q++) run += ssum[q][lane];
    float* Pb = &g_P[(size_t)(b * (N_ + 1)) * D_ + ch];
#pragma unroll
    for (int m = 0; m < 16; m++) {
        Pb[(size_t)(m0 + m) * D_] = run;
        run += g_S0[(b * N_ + si[m0 + m]) * D_ + ch];
    }
    if (w == 31) Pb[(size_t)N_ * D_] = run;
}

// merged weight-prep: Wfull (grammar) + Wcat/bcat (heads+out)
__global__ void k_weights(const float* __restrict__ relW, const float* __restrict__ relb,
                          const float* __restrict__ h1W, const float* __restrict__ h1b,
                          const float* __restrict__ outW, const float* __restrict__ outb) {
    const int W1 = KA_ * D_;
    const int W2 = W1 + 1024 * D_;
    int idx = blockIdx.x * 256 + threadIdx.x;
    if (idx < W1) {
        int row = idx / D_, e = idx % D_;
        float v;
        if (row < R_ * D_)            v = relW[idx];
        else if (row < R_ * D_ + R_)  v = relb[(row - R_ * D_) * D_ + e];
        else                          v = 0.f;
        g_Wfull[idx] = v;
    } else if (idx < W2) {
        int i = idx - W1;
        int k = i >> 10, n = i & 1023;
        g_Wcat[i] = (n < 768) ? h1W[((n >> 8) * D_ + k) * D_ + (n & 255)]
                              : outW[k * D_ + (n - 768)];
    } else if (idx < W2 + 1024) {
        int i = idx - W2;
        g_bcat[i] = (i < 768) ? h1b[(i >> 8) * D_ + (i & 255)] : outb[i - 768];
    }
}

// ---------------- tf32 helpers ----------------
__device__ __forceinline__ uint32_t f2tf32(float x) {
    uint32_t r;
    asm("cvt.rna.tf32.f32 %0, %1;" : "=r"(r) : "f"(x));
    return r;
}

__device__ __forceinline__ void mma_tf32(float* c, uint32_t a0, uint32_t a1,
                                         uint32_t a2, uint32_t a3,
                                         uint32_t b0, uint32_t b1) {
    asm volatile(
        "mma.sync.aligned.m16n8k8.row.col.f32.tf32.tf32.f32 "
        "{%0,%1,%2,%3}, {%4,%5,%6,%7}, {%8,%9}, {%0,%1,%2,%3};"
        : "+f"(c[0]), "+f"(c[1]), "+f"(c[2]), "+f"(c[3])
        : "r"(a0), "r"(a1), "r"(a2), "r"(a3), "r"(b0), "r"(b1));
}

// ---------------- band-restricted bitmask GEMM + A-row epilogue ----------------
// grid (8 ch-tiles of 32, 8 j-tiles of 64 SORTED rows, 8 b), 256 thr
__global__ void __launch_bounds__(256, 4) k_mgband() {
    __shared__ uint32_t BsH[32 * 36];
    __shared__ uint32_t mw[3][64];
    __shared__ int      sk0[64], sk1[64], ssid[64];
    __shared__ int      s_lo, s_hi;

    int b   = blockIdx.z;
    int j0  = blockIdx.y * 64;
    int ch0 = blockIdx.x * 32;
    int t    = threadIdx.x;
    int warp = t >> 5, lane = t & 31;
    int wm = warp >> 1;
    int wn = warp & 1;
    int qr = lane >> 2, qc = lane & 3;
    bool count_blk = (blockIdx.x == 0);

    if (t < 64) {
        sk0[t]  = g_k0s[b * N_ + j0 + t];
        sk1[t]  = g_k1s[b * N_ + j0 + t];
        ssid[t] = g_sidx[b * N_ + j0 + t];
    }
    __syncthreads();
    if (t < 32) {
        int lo = min(sk0[t], sk0[t + 32]);
        int hi = max(sk1[t], sk1[t + 32]);
#pragma unroll
        for (int o = 16; o; o >>= 1) {
            lo = min(lo, __shfl_xor_sync(0xffffffffu, lo, o));
            hi = max(hi, __shfl_xor_sync(0xffffffffu, hi, o));
        }
        if (t == 0) { s_lo = lo & ~31; s_hi = hi; }
    }
    __syncthreads();
    int klo = s_lo, khi = s_hi;

    float acc[3][2][4];
#pragma unroll
    for (int r = 0; r < 3; r++)
#pragma unroll
        for (int nt = 0; nt < 2; nt++)
#pragma unroll
            for (int f = 0; f < 4; f++) acc[r][nt][f] = 0.f;

    const uint32_t ONE = 0x3F800000u;
    int rb = wm * 16 + qr;

    for (int kt = klo; kt < khi; kt += 32) {
        int w = kt >> 5;
        if (t < 192) {
            int r = t >> 6, j = t & 63;
            mw[r][j] = g_mask[((size_t)(r * B_ + b) * N_ + j0 + j) * 16 + w];
        }
#pragma unroll
        for (int l = 0; l < 4; l++) {
            int id = t + l * 256;
            int k  = id >> 5, n = id & 31;
            int row = g_sidx[b * N_ + kt + k];
            float v = g_S0[(size_t)(b * N_ + row) * D_ + ch0 + n];
            BsH[n * 36 + k] = f2tf32(v);
        }
        __syncthreads();

        uint32_t s2a = mw[0][rb] >> qc, s2b = mw[0][rb + 8] >> qc;
        uint32_t s3a = mw[1][rb] >> qc, s3b = mw[1][rb + 8] >> qc;
        uint32_t s4a = mw[2][rb] >> qc, s4b = mw[2][rb + 8] >> qc;

#pragma unroll
        for (int ks = 0; ks < 32; ks += 8) {
            int k0 = ks + qc;
            uint32_t bh[4];
#pragma unroll
            for (int nt = 0; nt < 2; nt++) {
                int nb = wn * 16 + nt * 8 + qr;
                bh[nt*2+0] = BsH[nb * 36 + k0];
                bh[nt*2+1] = BsH[nb * 36 + k0 + 4];
            }
            {
                uint32_t a0 = ((s2a >> ks) & 1u)       ? ONE : 0u;
                uint32_t a1 = ((s2b >> ks) & 1u)       ? ONE : 0u;
                uint32_t a2 = ((s2a >> (ks + 4)) & 1u) ? ONE : 0u;
                uint32_t a3 = ((s2b >> (ks + 4)) & 1u) ? ONE : 0u;
                mma_tf32(acc[0][0], a0, a1, a2, a3, bh[0], bh[1]);
                mma_tf32(acc[0][1], a0, a1, a2, a3, bh[2], bh[3]);
            }
            {
                uint32_t a0 = ((s3a >> ks) & 1u)       ? ONE : 0u;
                uint32_t a1 = ((s3b >> ks) & 1u)       ? ONE : 0u;
                uint32_t a2 = ((s3a >> (ks + 4)) & 1u) ? ONE : 0u;
                uint32_t a3 = ((s3b >> (ks + 4)) & 1u) ? ONE : 0u;
                mma_tf32(acc[1][0], a0, a1, a2, a3, bh[0], bh[1]);
                mma_tf32(acc[1][1], a0, a1, a2, a3, bh[2], bh[3]);
            }
            {
                uint32_t a0 = ((s4a >> ks) & 1u)       ? ONE : 0u;
                uint32_t a1 = ((s4b >> ks) & 1u)       ? ONE : 0u;
                uint32_t a2 = ((s4a >> (ks + 4)) & 1u) ? ONE : 0u;
                uint32_t a3 = ((s4b >> (ks + 4)) & 1u) ? ONE : 0u;
                mma_tf32(acc[2][0], a0, a1, a2, a3, bh[0], bh[1]);
                mma_tf32(acc[2][1], a0, a1, a2, a3, bh[2], bh[3]);
            }
        }
        __syncthreads();
    }

    const float* Pb = &g_P[(size_t)(b * (N_ + 1)) * D_];
#pragma unroll
    for (int f = 0; f < 4; f++) {
        int rl  = wm * 16 + qr + ((f >= 2) ? 8 : 0);
        int oj  = ssid[rl];
        int k0r = sk0[rl], k1r = sk1[rl];
        int grow = b * N_ + oj;
        float* Ar = &g_A[(size_t)grow * KA_];
#pragma unroll
        for (int nt = 0; nt < 2; nt++) {
            int col = ch0 + wn * 16 + nt * 8 + qc * 2 + (f & 1);
            float p0  = Pb[(size_t)k0r * D_ + col];
            float p1  = Pb[(size_t)k1r * D_ + col];
            float tot = Pb[(size_t)N_ * D_ + col];
            float sj  = g_S0[(size_t)grow * D_ + col];
            float a2v = acc[0][nt][f];
            float a3v = acc[1][nt][f];
            float a4v = acc[2][nt][f];
            Ar[0 * D_ + col] = p0;
            Ar[1 * D_ + col] = tot - p1;
            Ar[2 * D_ + col] = a2v;
            Ar[3 * D_ + col] = a3v;
            Ar[4 * D_ + col] = a4v;
            Ar[5 * D_ + col] = (p1 - p0 - sj) - a2v - a3v - a4v;
        }
    }
    if (count_blk && t < 64) {
        int k0r = sk0[t], k1r = sk1[t];
        int w0 = k0r >> 5, w1 = (k1r + 31) >> 5;
        int n2 = 0, n3 = 0, n4 = 0;
        for (int w = w0; w < w1; w++) {
            n2 += __popc(g_mask[((size_t)(0 * B_ + b) * N_ + j0 + t) * 16 + w]);
            n3 += __popc(g_mask[((size_t)(1 * B_ + b) * N_ + j0 + t) * 16 + w]);
            n4 += __popc(g_mask[((size_t)(2 * B_ + b) * N_ + j0 + t) * 16 + w]);
        }
        int oj = ssid[t];
        float* Ar = &g_A[(size_t)(b * N_ + oj) * KA_ + R_ * D_];
#pragma unroll
        for (int c = 0; c < 32; c++) {
            float cv = 0.f;
            if (c == 0)      cv = (float)k0r;
            else if (c == 1) cv = (float)(N_ - k1r);
            else if (c == 2) cv = (float)n2;
            else if (c == 3) cv = (float)n3;
            else if (c == 4) cv = (float)n4;
            else if (c == 5) cv = (float)((k1r - k0r - 1) - n2 - n3 - n4);
            Ar[c] = cv;
        }
    }
}

// ---------------- main GEMMs: tf32 3-pass, conflict-free packed smem ----------------
// Packing: per (row, ks-group g, slot): float4 {hi(8g+qc), hi(8g+qc+4), lo(8g+qc), lo(8g+qc+4)}
// where slot = qc ^ (row&3). Row stride 20 float4 (4*20 ≡ 16 mod 32) -> fragment
// LDS.128 per 8-lane phase hits 8 distinct bank-groups (conflict-free).
#define S4_ 20

template<int MODE, int BNt>
__global__ void __launch_bounds__(256) mgemm2(
        const float* __restrict__ A, int lda,
        const float* __restrict__ Bm, int ldb, int K,
        const float* __restrict__ addp,
        float* __restrict__ C, float* __restrict__ C2) {
    constexpr int HALF = BNt / 2;
    constexpr int NT   = HALF / 8;
    extern __shared__ float4 sm4[];
    float4* AsP = sm4;               // [128][S4_]
    float4* BsP = sm4 + 128 * S4_;   // [BNt][S4_]

    int t    = threadIdx.x;
    int warp = t >> 5, lane = t & 31;
    int wm   = warp >> 1;
    int wn   = warp & 1;
    int bm0  = blockIdx.y * 128;
    int bn0  = blockIdx.x * BNt;
    int qr   = lane >> 2;
    int qc   = lane & 3;
    int sfr  = qc ^ (qr & 3);        // fragment slot

    float acc[2][NT][4];
#pragma unroll
    for (int mt = 0; mt < 2; mt++)
#pragma unroll
        for (int nt = 0; nt < NT; nt++)
#pragma unroll
            for (int f = 0; f < 4; f++) acc[mt][nt][f] = 0.f;

    for (int kt = 0; kt < K; kt += 32) {
        // stage A [128 x 32] -> packed hi/lo
#pragma unroll
        for (int l = 0; l < 4; l++) {
            int id   = t + l * 256;
            int row  = id >> 3;
            int kq   = (id & 7) * 4;
            int g    = kq >> 3;
            int half = (kq >> 2) & 1;
            float4 v = *(const float4*)&A[(size_t)(bm0 + row) * lda + kt + kq];
            float* base = (float*)&AsP[row * S4_ + g * 4];
            float fe[4] = {v.x, v.y, v.z, v.w};
            int rs = row & 3;
#pragma unroll
            for (int j = 0; j < 4; j++) {
                int slot = j ^ rs;
                uint32_t h = f2tf32(fe[j]);
                base[slot * 4 + half]     = __uint_as_float(h);
                base[slot * 4 + 2 + half] = __uint_as_float(f2tf32(fe[j] - __uint_as_float(h)));
            }
        }
        // stage B [32 x BNt] -> packed hi/lo at [n][g][slot]
#pragma unroll
        for (int l = 0; l < (BNt * 32) / 256; l++) {
            int id   = t + l * 256;
            int k    = id / BNt;
            int n    = id % BNt;
            int g    = k >> 3;
            int half = (k >> 2) & 1;
            int slot = (k & 3) ^ (n & 3);
            float v = Bm[(size_t)(kt + k) * ldb + bn0 + n];
            uint32_t h = f2tf32(v);
            float* base = (float*)&BsP[n * S4_ + g * 4];
            base[slot * 4 + half]     = __uint_as_float(h);
            base[slot * 4 + 2 + half] = __uint_as_float(f2tf32(v - __uint_as_float(h)));
        }
        __syncthreads();

#pragma unroll
        for (int g = 0; g < 4; g++) {
            uint32_t ahi[8], alo[8];
#pragma unroll
            for (int mt = 0; mt < 2; mt++) {
                int rb = wm * 32 + mt * 16 + qr;
                float4 va = AsP[rb * S4_ + g * 4 + sfr];
                float4 vb = AsP[(rb + 8) * S4_ + g * 4 + sfr];
                ahi[mt*4+0] = __float_as_uint(va.x);
                ahi[mt*4+1] = __float_as_uint(vb.x);
                ahi[mt*4+2] = __float_as_uint(va.y);
                ahi[mt*4+3] = __float_as_uint(vb.y);
                alo[mt*4+0] = __float_as_uint(va.z);
                alo[mt*4+1] = __float_as_uint(vb.z);
                alo[mt*4+2] = __float_as_uint(va.w);
                alo[mt*4+3] = __float_as_uint(vb.w);
            }
            uint32_t bhi[2*NT], blo[2*NT];
#pragma unroll
            for (int nt = 0; nt < NT; nt++) {
                int nb = wn * HALF + nt * 8 + qr;
                float4 v = BsP[nb * S4_ + g * 4 + sfr];
                bhi[nt*2+0] = __float_as_uint(v.x);
                bhi[nt*2+1] = __float_as_uint(v.y);
                blo[nt*2+0] = __float_as_uint(v.z);
                blo[nt*2+1] = __float_as_uint(v.w);
            }
#pragma unroll
            for (int mt = 0; mt < 2; mt++)
#pragma unroll
                for (int nt = 0; nt < NT; nt++) {
                    float* c = acc[mt][nt];
                    mma_tf32(c, ahi[mt*4], ahi[mt*4+1], ahi[mt*4+2], ahi[mt*4+3],
                             bhi[nt*2], bhi[nt*2+1]);
                    mma_tf32(c, alo[mt*4], alo[mt*4+1], alo[mt*4+2], alo[mt*4+3],
                             bhi[nt*2], bhi[nt*2+1]);
                    mma_tf32(c, ahi[mt*4], ahi[mt*4+1], ahi[mt*4+2], ahi[mt*4+3],
                             blo[nt*2], blo[nt*2+1]);
                }
        }
        __syncthreads();
    }

#pragma unroll
    for (int mt = 0; mt < 2; mt++) {
#pragma unroll
        for (int f = 0; f < 4; f++) {
            int row = bm0 + wm * 32 + mt * 16 + qr + ((f >= 2) ? 8 : 0);
#pragma unroll
            for (int nt = 0; nt < NT; nt++) {
                int col = bn0 + wn * HALF + nt * 8 + qc * 2 + (f & 1);
                float v = acc[mt][nt][f];
                if (MODE == 0) {
                    v += addp[(size_t)row * D_ + col];
                    C[(size_t)row * D_ + col] = v;
                } else {
                    v += g_bcat[col];
                    if (bn0 < 768) {
                        v = 0.5f * v * (1.f + erff(v * 0.70710678118654752440f));
                        C[(size_t)row * 768 + col] = v;
                    } else {
                        C2[(size_t)row * D_ + (col - 768)] = v;
                    }
                }
            }
        }
    }
}

__global__ void k_interp(const float* __restrict__ h2W, const float* __restrict__ h2b,
                         float* __restrict__ out) {
    int row  = blockIdx.x;
    int wid  = threadIdx.x >> 5;
    int lane = threadIdx.x & 31;
    const float* hrow = &g_H[(size_t)row * (3 * D_) + wid * D_];
    const float* w    = &h2W[wid * D_];
    float s = 0.f;
    for (int e = lane; e < D_; e += 32) s += hrow[e] * w[e];
#pragma unroll
    for (int o = 16; o; o >>= 1) s += __shfl_xor_sync(0xffffffffu, s, o);
    if (lane == 0) out[OFF_INTERP + wid * BN_ + row] = s + h2b[wid];
}

// ---------------- launch ----------------
#define SMB(BNt) ((128 + (BNt)) * S4_ * 16)

extern "C" void kernel_launch(void* const* d_in, const int* in_sizes, int n_in,
                              void* d_out, int out_size) {
    const int*   ids  = (const int*)  d_in[0];
    const float* pos  = (const float*)d_in[1];
    const float* symt = (const float*)d_in[2];
    const float* layt = (const float*)d_in[3];
    const float* relW = (const float*)d_in[4];
    const float* relb = (const float*)d_in[5];
    const float* h1W  = (const float*)d_in[6];
    const float* h1b  = (const float*)d_in[7];
    const float* h2W  = (const float*)d_in[8];
    const float* h2b  = (const float*)d_in[9];
    const float* outW = (const float*)d_in[10];
    const float* outb = (const float*)d_in[11];
    float* out = (float*)d_out;

    float *pA, *pW, *pWc, *pH, *pS0;
    cudaGetSymbolAddress((void**)&pA,  g_A);
    cudaGetSymbolAddress((void**)&pW,  g_Wfull);
    cudaGetSymbolAddress((void**)&pWc, g_Wcat);
    cudaGetSymbolAddress((void**)&pH,  g_H);
    cudaGetSymbolAddress((void**)&pS0, g_S0);

    cudaFuncSetAttribute((const void*)mgemm2<0,32>,
                         cudaFuncAttributeMaxDynamicSharedMemorySize, SMB(32));
    cudaFuncSetAttribute((const void*)mgemm2<1,64>,
                         cudaFuncAttributeMaxDynamicSharedMemorySize, SMB(64));

    // slot #3 (0-indexed) = k_maskb -> profiled by ncu
    k_embed <<<BN_, D_>>>(ids, symt, layt);
    k_sort  <<<B_, N_>>>(pos);
    k_prefix<<<B_ * 8, 1024>>>();
    k_maskb <<<dim3(16, 8), 256>>>();
    k_mgband<<<dim3(8, 8, 8), 256>>>();
    {
        int total = KA_ * D_ + 1024 * D_ + 1024;
        k_weights<<<(total + 255) / 256, 256>>>(relW, relb, h1W, h1b, outW, outb);
    }

    float* d_sym = out + OFF_SYM;
    // grammar: symbols = S0 + A @ Wfull  (BN=32 -> 256 blocks)
    mgemm2<0,32><<<dim3(D_ / 32, BN_ / 128), 256, SMB(32)>>>(
        pA, KA_, pW, D_, KA_, pS0, d_sym, nullptr);
    // fused heads (gelu -> g_H) + output projection (-> out)
    mgemm2<1,64><<<dim3(1024 / 64, BN_ / 128), 256, SMB(64)>>>(
        d_sym, D_, pWc, 1024, D_, nullptr, pH, out);

    k_interp<<<BN_, 96>>>(h2W, h2b, out);
}